// round 13
// baseline (speedup 1.0000x reference)
#include <cuda_runtime.h>
#include <cuda_fp16.h>
#include <cstdint>

#define BB 16
#define NN 4096
#define SS 512
#define NSAMP 32
#define POS (NSAMP*SS)       // 16384 positions per batch; pos = s*32 + ns
#define PTOT (BB*POS)
#define R2 0.16f
#define NGRP 512             // POS/32 groups per batch; group g == centroid s

// Fragment layout: [b][g][mt(2)][ks(4)][reg(4)][lane(32)] uint32 (half2)
#define FRAG_BATCH (NGRP*2*4*4*32)   // 524288 uint32 per batch

// ---------------- scratch (device globals; no allocation allowed) ----------
__device__ uint32_t g_x0F[BB*FRAG_BATCH];   // raw W0*feat, fragment layout
__device__ uint32_t g_x1F[BB*FRAG_BATCH];   // raw W1*y1,   fragment layout
__device__ float g_gmax[BB*128*SS];         // [b][o][s]
__device__ float g_gmin[BB*128*SS];
__device__ float g_fs[6], g_gm[21];
__device__ float g_sum1[64], g_sq1[64];
__device__ float g_sum2[128], g_sq2[128];

// ---------------- helpers ---------------------------------------------------
__device__ __forceinline__ uint32_t smem_u32(const void* p) {
    return (uint32_t)__cvta_generic_to_shared(p);
}
__device__ __forceinline__ void mma_f16(float d[4], const uint32_t a[4],
                                        uint32_t b0, uint32_t b1) {
    asm volatile(
        "mma.sync.aligned.m16n8k16.row.col.f32.f16.f16.f32 "
        "{%0,%1,%2,%3}, {%4,%5,%6,%7}, {%8,%9}, {%0,%1,%2,%3};"
        : "+f"(d[0]), "+f"(d[1]), "+f"(d[2]), "+f"(d[3])
        : "r"(a[0]), "r"(a[1]), "r"(a[2]), "r"(a[3]), "r"(b0), "r"(b1));
}
#define LDSM_X2(r0,r1,addr) \
    asm volatile("ldmatrix.sync.aligned.m8n8.x2.shared.b16 {%0,%1}, [%2];" \
        : "=r"(r0), "=r"(r1) : "r"(addr))

// ---------------- FPS: 512 threads x 8 pts/thread --------------------------
// smem: xyz (3*NN floats) | sred [2][32] u64 (upper 16/phase = pad) | sfarh
extern "C" __global__ __launch_bounds__(512)
void fps_kernel(const float* __restrict__ xyz, float* __restrict__ out_xyz) {
    extern __shared__ float fsh[];
    float* sx = fsh;
    float* sy = fsh + NN;
    float* sz = fsh + 2 * NN;
    unsigned long long* sred = (unsigned long long*)(fsh + 3 * NN); // [2][32]=512B
    int* sfarh = (int*)(fsh + 3 * NN + 128);                        // [512]

    int t = threadIdx.x, b = blockIdx.x, lane = t & 31, warp = t >> 5; // 16 warps
    const float* xb = xyz + (size_t)b * 3 * NN;

    // graph replay: reset global stats accumulators (block 0 only)
    if (b == 0) {
        if (t < 21) g_gm[t] = 0.f;
        else if (t < 27) g_fs[t - 21] = 0.f;
        if (t < 64) { g_sum1[t] = 0.f; g_sq1[t] = 0.f; }
        if (t < 128){ g_sum2[t] = 0.f; g_sq2[t] = 0.f; }
    }
    // pad upper 16 entries of each phase: value 0, idx 0xffffffff
    if (t < 64) {
        int ph = t >> 5, sl = t & 31;
        if (sl >= 16) sred[ph * 32 + sl] = 0x00000000FFFFFFFFull;
    }

    float px[8], py[8], pz[8], dist[8];
#pragma unroll
    for (int k = 0; k < 8; k++) {
        int i = t + k * 512;
        float x = xb[i], y = xb[NN + i], z = xb[2 * NN + i];
        px[k] = x; py[k] = y; pz[k] = z;
        sx[i] = x; sy[i] = y; sz[i] = z;
        dist[k] = 1e10f;
    }
    __syncthreads();

    int far = 0;
    for (int s = 0; s < SS; s++) {
        if (t == 0) sfarh[s] = far;
        float cx = sx[far], cy = sy[far], cz = sz[far];
        float bv; int bi;
        {
            float dx = px[0]-cx, dy = py[0]-cy, dz = pz[0]-cz;
            float d = dx*dx + dy*dy + dz*dz;
            float nd = fminf(dist[0], d); dist[0] = nd;
            bv = nd; bi = t;
        }
#pragma unroll
        for (int k = 1; k < 8; k++) {
            float dx = px[k]-cx, dy = py[k]-cy, dz = pz[k]-cz;
            float d = dx*dx + dy*dy + dz*dz;
            float nd = fminf(dist[k], d); dist[k] = nd;
            if (nd > bv) { bv = nd; bi = t + k * 512; }
        }
        unsigned uv = __float_as_uint(bv);
        unsigned wm = __reduce_max_sync(0xffffffffu, uv);
        unsigned cand = (uv == wm) ? (unsigned)bi : 0xffffffffu;
        unsigned wi = __reduce_min_sync(0xffffffffu, cand);
        if (lane == 0)
            sred[(s & 1) * 32 + warp] = ((unsigned long long)wm << 32) | wi;
        __syncthreads();
        unsigned long long e = sred[(s & 1) * 32 + lane];
        unsigned v = (unsigned)(e >> 32), ix = (unsigned)e;
        unsigned m2 = __reduce_max_sync(0xffffffffu, v);
        unsigned c2 = (v == m2) ? ix : 0xffffffffu;
        far = (int)__reduce_min_sync(0xffffffffu, c2);
    }
    __syncthreads();
    if (t < SS) {
        int i = sfarh[t];
        out_xyz[(b * 3 + 0) * SS + t] = sx[i];
        out_xyz[(b * 3 + 1) * SS + t] = sy[i];
        out_xyz[(b * 3 + 2) * SS + t] = sz[i];
    }
}

// ---------------- ball query + fused layer0 (fragment-layout out) ----------
#define BALL_SMEM_F (7*NN + 384 + 32*32*6 + 32*27)
extern "C" __global__ __launch_bounds__(1024)
void ball_kernel(const float* __restrict__ xyz, const float* __restrict__ pts,
                 const float* __restrict__ new_xyz, const float* __restrict__ w0) {
    extern __shared__ float sh[];
    float* sx   = sh;
    float* sy   = sh + NN;
    float* sz   = sh + 2 * NN;
    float* spp  = sh + 3 * NN;
    float* sp0  = sh + 4 * NN;
    float* sp1  = sh + 5 * NN;
    float* sp2  = sh + 6 * NN;
    float* sw   = sh + 7 * NN;
    float* swf  = sw + 384;
    float* sred = swf + 32 * 32 * 6;

    int b = blockIdx.x, chunk = blockIdx.y;
    int t = threadIdx.x;
    const float* xb = xyz + (size_t)b * 3 * NN;
    const float* pb = pts + (size_t)b * 3 * NN;

    if (t < 384) sw[t] = w0[t];
    for (int i = t; i < NN; i += 1024) {
        float x = xb[i], y = xb[NN + i], z = xb[2 * NN + i];
        sx[i] = x; sy[i] = y; sz[i] = z;
        spp[i] = x * x + y * y + z * z;
        sp0[i] = pb[i]; sp1[i] = pb[NN + i]; sp2[i] = pb[2 * NN + i];
    }
    __syncthreads();

    int lane = t & 31, warp = t >> 5;
    float* wslots = swf + warp * 192;

    float gm[21];
    float fs[6];
#pragma unroll
    for (int k = 0; k < 21; k++) gm[k] = 0.f;
#pragma unroll
    for (int k = 0; k < 6; k++) fs[k] = 0.f;

    uint32_t* x0b = g_x0F + (size_t)b * FRAG_BATCH;
    int mt = lane >> 4, gid8 = lane & 7, rh = (lane >> 3) & 1;

    for (int q = 0; q < 2; q++) {
        int s = chunk * 64 + q * 32 + warp;
        float cx = new_xyz[(b * 3 + 0) * SS + s];
        float cy = new_xyz[(b * 3 + 1) * SS + s];
        float cz = new_xyz[(b * 3 + 2) * SS + s];
        float cc = cx * cx + cy * cy + cz * cz;

        int count = 0;
        int first_i = 0;
        for (int base = 0; base < NN; base += 32) {
            int i = base + lane;
            float dot = cx * sx[i] + cy * sy[i] + cz * sz[i];
            float sum2 = __fadd_rn(cc, spp[i]);
            float sqr = __fsub_rn(sum2, 2.0f * dot);
            bool pred = (sqr <= R2);
            unsigned mask = __ballot_sync(0xffffffffu, pred);
            if (count == 0 && mask) {
                int src = __ffs(mask) - 1;
                first_i = __shfl_sync(0xffffffffu, i, src);
            }
            int rank = __popc(mask & ((1u << lane) - 1u));
            int slot = count + rank;
            if (pred && slot < NSAMP) {
                float* d = wslots + slot * 6;
                d[0] = sx[i] - cx; d[1] = sy[i] - cy; d[2] = sz[i] - cz;
                d[3] = sp0[i];     d[4] = sp1[i];     d[5] = sp2[i];
            }
            count += __popc(mask);
            if (count >= NSAMP) break;
        }
        if (count < NSAMP && lane >= count) {
            int i = first_i;
            float* d = wslots + lane * 6;
            d[0] = sx[i] - cx; d[1] = sy[i] - cy; d[2] = sz[i] - cz;
            d[3] = sp0[i];     d[4] = sp1[i];     d[5] = sp2[i];
        }
        __syncwarp();

        float f[6];
#pragma unroll
        for (int c = 0; c < 6; c++) f[c] = wslots[lane * 6 + c];
        {
            int k = 0;
#pragma unroll
            for (int c = 0; c < 6; c++) {
                fs[c] += f[c];
#pragma unroll
                for (int d = c; d < 6; d++) gm[k++] += f[c] * f[d];
            }
        }
#pragma unroll 2
        for (int jc = 0; jc < 8; jc++) {
            float v[8];
#pragma unroll
            for (int jj = 0; jj < 8; jj++) {
                int o = jc * 8 + jj;
                const float2* wr = (const float2*)&sw[o * 6];
                float2 w01 = wr[0], w23 = wr[1], w45 = wr[2];
                v[jj] = w01.x * f[0] + w01.y * f[1] + w23.x * f[2]
                      + w23.y * f[3] + w45.x * f[4] + w45.y * f[5];
            }
            int ks = jc >> 1, kh = jc & 1;
            uint4 u;
            uint32_t* up = (uint32_t*)&u;
#pragma unroll
            for (int i = 0; i < 4; i++) {
                __half2 h = __floats2half2_rn(v[2*i], v[2*i+1]);
                up[i] = *(uint32_t*)&h;
            }
            size_t idx = ((((size_t)s * 2 + mt) * 4 + ks) * 4 + (kh * 2 + rh)) * 32
                       + gid8 * 4;
            *(uint4*)&x0b[idx] = u;
        }
        __syncwarp();
    }

#pragma unroll
    for (int k = 0; k < 21; k++)
#pragma unroll
        for (int off = 16; off; off >>= 1)
            gm[k] += __shfl_xor_sync(0xffffffffu, gm[k], off);
#pragma unroll
    for (int k = 0; k < 6; k++)
#pragma unroll
        for (int off = 16; off; off >>= 1)
            fs[k] += __shfl_xor_sync(0xffffffffu, fs[k], off);
    if (lane == 0) {
#pragma unroll
        for (int k = 0; k < 21; k++) sred[warp * 27 + k] = gm[k];
#pragma unroll
        for (int k = 0; k < 6; k++)  sred[warp * 27 + 21 + k] = fs[k];
    }
    __syncthreads();
    if (t < 27) {
        float v = 0.f;
#pragma unroll 8
        for (int w = 0; w < 32; w++) v += sred[w * 27 + t];
        if (t < 21) atomicAdd(&g_gm[t], v);
        else        atomicAdd(&g_fs[t - 21], v);
    }
}

// ---------------- fp16 mma.sync layer kernels (B hoisted to registers) -----
// A fragments loaded from global; B fragments ldmatrix'd ONCE before the loop.
template <int L>
__global__ __launch_bounds__(256, 1) void mma_layer_kernel(
    const float* __restrict__ w,       // w1 / w2 : [COUT][64]
    const float* __restrict__ w0,      // L=1 only (Gram matvec)
    const float* __restrict__ gg,      // g0 / g1
    const float* __restrict__ gbeta)   // beta0 / beta1
{
    constexpr int COUT  = (L == 1) ? 64 : 128;
    constexpr int TILES = (L == 1) ? 4 : 8;

    extern __shared__ __align__(16) char dsmc[];
    __half* sw = (__half*)dsmc;                          // [COUT][72]
    float* sred_s = (float*)(dsmc + COUT * 144);         // [8][64]
    float* sred_q = sred_s + 8 * 64;                     // [8][64]
    __shared__ float san[64], scn[64];

    int t = threadIdx.x;
    int warp = t >> 5, lane = t & 31;
    int gid = lane >> 2, tig = lane & 3;

    int b = blockIdx.x >> 4, chunk = blockIdx.x & 15;
    int ob = (L == 1) ? 0 : (warp & 1) * 64;

    // stage W -> half smem [n][72] (once per CTA)
    for (int e = t; e < COUT * 8; e += 256) {
        int n = e >> 3, q = e & 7;
        const float4* wr = (const float4*)(w + n * 64 + q * 8);
        float4 wa = wr[0], wb = wr[1];
        uint4 u;
        uint32_t* up = (uint32_t*)&u;
        __half2 h0 = __floats2half2_rn(wa.x, wa.y); up[0] = *(uint32_t*)&h0;
        __half2 h1 = __floats2half2_rn(wa.z, wa.w); up[1] = *(uint32_t*)&h1;
        __half2 h2 = __floats2half2_rn(wb.x, wb.y); up[2] = *(uint32_t*)&h2;
        __half2 h3 = __floats2half2_rn(wb.z, wb.w); up[3] = *(uint32_t*)&h3;
        *(uint4*)&sw[n * 72 + q * 8] = u;
    }
    for (int e = t; e < 512; e += 256) { sred_s[e] = 0.f; sred_q[e] = 0.f; }

    // fused finalize of previous layer's BN -> san/scn
    const float invP = 1.0f / (float)PTOT;
    if (t < 64) {
        float m, var;
        if (L == 1) {
            float wv[6];
#pragma unroll
            for (int c = 0; c < 6; c++) wv[c] = w0[t * 6 + c];
            m = 0.f;
#pragma unroll
            for (int c = 0; c < 6; c++) m += wv[c] * g_fs[c];
            m *= invP;
            float e2 = 0.f;
            int k = 0;
#pragma unroll
            for (int c = 0; c < 6; c++)
#pragma unroll
                for (int d = c; d < 6; d++) {
                    float gcd = g_gm[k++];
                    e2 += (d == c) ? wv[c] * wv[c] * gcd
                                   : 2.f * wv[c] * wv[d] * gcd;
                }
            e2 *= invP;
            var = e2 - m * m;
        } else {
            m = g_sum1[t] * invP;
            var = g_sq1[t] * invP - m * m;
        }
        float av = gg[t] * rsqrtf(var + 1e-5f);
        san[t] = av;
        scn[t] = gbeta[t] - m * av;
    }
    __syncthreads();

    const uint32_t* xin = ((L == 1) ? g_x0F : g_x1F) + (size_t)b * FRAG_BATCH;
    uint32_t* xout = g_x1F + (size_t)b * FRAG_BATCH;
    uint32_t sw_b = smem_u32(sw);
    int b_row  = ob + (lane & 7);
    int b_koff = ((lane >> 3) & 1) * 8;

    // ---- hoist B fragments to registers (tile-invariant) ----
    uint32_t bfr[4][8][2];
#pragma unroll
    for (int ks = 0; ks < 4; ks++) {
        int k0 = ks * 16;
#pragma unroll
        for (int nt = 0; nt < 8; nt++) {
            uint32_t baddr = sw_b + (uint32_t)(((b_row + nt * 8) * 72 + k0 + b_koff) * 2);
            LDSM_X2(bfr[ks][nt][0], bfr[ks][nt][1], baddr);
        }
    }

    for (int tile = 0; tile < TILES; tile++) {
        int g = (L == 1) ? (chunk * 32 + tile * 8 + warp)
                         : (chunk * 32 + tile * 4 + (warp >> 1));

        // ---- load A fragments from global (coalesced 128B lines) ----
        uint32_t afr[2][4][4];
#pragma unroll
        for (int mt = 0; mt < 2; mt++)
#pragma unroll
            for (int ks = 0; ks < 4; ks++) {
                const uint32_t* p = xin + ((((size_t)g * 2 + mt) * 4 + ks) * 4) * 32 + lane;
                afr[mt][ks][0] = p[0];
                afr[mt][ks][1] = p[32];
                afr[mt][ks][2] = p[64];
                afr[mt][ks][3] = p[96];
            }
        // ---- BN + relu in registers ----
#pragma unroll
        for (int mt = 0; mt < 2; mt++)
#pragma unroll
            for (int ks = 0; ks < 4; ks++)
#pragma unroll
                for (int j = 0; j < 4; j++) {
                    int c0 = ks * 16 + (j >> 1) * 8 + tig * 2;
                    __half2 h = *(__half2*)&afr[mt][ks][j];
                    float2 f = __half22float2(h);
                    f.x = fmaxf(0.f, san[c0]     * f.x + scn[c0]);
                    f.y = fmaxf(0.f, san[c0 + 1] * f.y + scn[c0 + 1]);
                    __half2 ho = __floats2half2_rn(f.x, f.y);
                    afr[mt][ks][j] = *(uint32_t*)&ho;
                }

        // ---- MMA ----
        float acc[2][8][4];
#pragma unroll
        for (int mt = 0; mt < 2; mt++)
#pragma unroll
            for (int nt = 0; nt < 8; nt++)
#pragma unroll
                for (int k = 0; k < 4; k++) acc[mt][nt][k] = 0.f;
#pragma unroll
        for (int ks = 0; ks < 4; ks++) {
#pragma unroll
            for (int nt = 0; nt < 8; nt++) {
                mma_f16(acc[0][nt], afr[0][ks], bfr[ks][nt][0], bfr[ks][nt][1]);
                mma_f16(acc[1][nt], afr[1][ks], bfr[ks][nt][0], bfr[ks][nt][1]);
            }
        }

        // ---- epilogue ----
#pragma unroll
        for (int nt = 0; nt < 8; nt++) {
            float se = 0.f, so = 0.f, qe = 0.f, qo = 0.f;
            float mxe = -1e30f, mxo = -1e30f, mne = 1e30f, mno = 1e30f;
#pragma unroll
            for (int mt = 0; mt < 2; mt++) {
                float v0 = acc[mt][nt][0], v1 = acc[mt][nt][1];
                float v2 = acc[mt][nt][2], v3 = acc[mt][nt][3];
                se += v0 + v2; so += v1 + v3;
                qe += v0*v0 + v2*v2; qo += v1*v1 + v3*v3;
                if (L == 1) {
                    __half2 h01 = __floats2half2_rn(v0, v1);
                    __half2 h23 = __floats2half2_rn(v2, v3);
                    size_t base = ((((size_t)g * 2 + mt) * 4 + (nt >> 1)) * 4
                                  + (nt & 1) * 2) * 32 + lane;
                    xout[base]      = *(uint32_t*)&h01;
                    xout[base + 32] = *(uint32_t*)&h23;
                } else {
                    mxe = fmaxf(mxe, fmaxf(v0, v2)); mne = fminf(mne, fminf(v0, v2));
                    mxo = fmaxf(mxo, fmaxf(v1, v3)); mno = fminf(mno, fminf(v1, v3));
                }
            }
#pragma unroll
            for (int off = 4; off < 32; off <<= 1) {
                se += __shfl_xor_sync(0xffffffffu, se, off);
                so += __shfl_xor_sync(0xffffffffu, so, off);
                qe += __shfl_xor_sync(0xffffffffu, qe, off);
                qo += __shfl_xor_sync(0xffffffffu, qo, off);
                if (L == 2) {
                    mxe = fmaxf(mxe, __shfl_xor_sync(0xffffffffu, mxe, off));
                    mxo = fmaxf(mxo, __shfl_xor_sync(0xffffffffu, mxo, off));
                    mne = fminf(mne, __shfl_xor_sync(0xffffffffu, mne, off));
                    mno = fminf(mno, __shfl_xor_sync(0xffffffffu, mno, off));
                }
            }
            if (gid == 0) {
                int lc = nt * 8 + 2 * tig;
                sred_s[warp * 64 + lc]     += se;
                sred_s[warp * 64 + lc + 1] += so;
                sred_q[warp * 64 + lc]     += qe;
                sred_q[warp * 64 + lc + 1] += qo;
                if (L == 2) {
                    int o = ob + lc;
                    g_gmax[(size_t)(b * 128 + o) * SS + g]     = mxe;
                    g_gmax[(size_t)(b * 128 + o + 1) * SS + g] = mxo;
                    g_gmin[(size_t)(b * 128 + o) * SS + g]     = mne;
                    g_gmin[(size_t)(b * 128 + o + 1) * SS + g] = mno;
                }
            }
        }
    }
    __syncthreads();

    if (L == 1) {
        if (t < 64) {
            float s = 0.f;
#pragma unroll
            for (int w8 = 0; w8 < 8; w8++) s += sred_s[w8 * 64 + t];
            atomicAdd(&g_sum1[t], s);
        } else if (t < 128) {
            int c = t - 64;
            float q = 0.f;
#pragma unroll
            for (int w8 = 0; w8 < 8; w8++) q += sred_q[w8 * 64 + c];
            atomicAdd(&g_sq1[c], q);
        }
    } else {
        if (t < 128) {
            int par = t >> 6, lc = t & 63;
            float s = 0.f;
#pragma unroll
            for (int j = 0; j < 4; j++) s += sred_s[(2 * j + par) * 64 + lc];
            atomicAdd(&g_sum2[t], s);
        } else {
            int c = t - 128;
            int par = c >> 6, lc = c & 63;
            float q = 0.f;
#pragma unroll
            for (int j = 0; j < 4; j++) q += sred_q[(2 * j + par) * 64 + lc];
            atomicAdd(&g_sq2[c], q);
        }
    }
}

// ---------------- final: fused finalize2 + affine + relu on pooled ---------
__global__ __launch_bounds__(256) void final_kernel(float* __restrict__ out,
                                                    const float* __restrict__ g2,
                                                    const float* __restrict__ beta2) {
    int idx = blockIdx.x * 256 + threadIdx.x;   // (b,o,s)
    int o = (idx >> 9) & 127;
    const float invP = 1.0f / (float)PTOT;
    float m = g_sum2[o] * invP;
    float v = g_sq2[o] * invP - m * m;
    float av = g2[o] * rsqrtf(v + 1e-5f);
    float cv = beta2[o] - m * av;
    float mm = (av >= 0.f) ? g_gmax[idx] : g_gmin[idx];
    out[BB * 3 * SS + idx] = fmaxf(av * mm + cv, 0.f);
}

// ---------------- launch ----------------------------------------------------
extern "C" void kernel_launch(void* const* d_in, const int* in_sizes, int n_in,
                              void* d_out, int out_size) {
    const float* xyz   = (const float*)d_in[0];
    const float* pts   = (const float*)d_in[1];
    const float* w0    = (const float*)d_in[2];
    const float* g0    = (const float*)d_in[4];
    const float* beta0 = (const float*)d_in[5];
    const float* w1    = (const float*)d_in[6];
    const float* g1    = (const float*)d_in[8];
    const float* beta1 = (const float*)d_in[9];
    const float* w2    = (const float*)d_in[10];
    const float* g2    = (const float*)d_in[12];
    const float* beta2 = (const float*)d_in[13];
    float* out = (float*)d_out;

    const int FPS_SMEM = 3 * NN * 4 + 512 + SS * 4;
    const int SMEM_L1  = 64 * 144 + 2 * 8 * 64 * 4;    // ~13.3KB
    const int SMEM_L2  = 128 * 144 + 2 * 8 * 64 * 4;   // ~22.5KB

    cudaFuncSetAttribute(fps_kernel, cudaFuncAttributeMaxDynamicSharedMemorySize,
                         FPS_SMEM);
    cudaFuncSetAttribute(ball_kernel, cudaFuncAttributeMaxDynamicSharedMemorySize,
                         BALL_SMEM_F * 4);
    cudaFuncSetAttribute(mma_layer_kernel<1>, cudaFuncAttributeMaxDynamicSharedMemorySize,
                         SMEM_L1);
    cudaFuncSetAttribute(mma_layer_kernel<2>, cudaFuncAttributeMaxDynamicSharedMemorySize,
                         SMEM_L2);

    fps_kernel<<<BB, 512, FPS_SMEM>>>(xyz, out);
    ball_kernel<<<dim3(BB, 8), 1024, BALL_SMEM_F * 4>>>(xyz, pts, out, w0);
    mma_layer_kernel<1><<<256, 256, SMEM_L1>>>(w1, w0, g0, beta0);
    mma_layer_kernel<2><<<256, 256, SMEM_L2>>>(w2, w0, g1, beta1);
    final_kernel<<<(BB * 128 * SS) / 256, 256>>>(out, g2, beta2);
}

// round 16
// speedup vs baseline: 1.0413x; 1.0413x over previous
#include <cuda_runtime.h>
#include <cuda_fp16.h>
#include <cstdint>

#define BB 16
#define NN 4096
#define SS 512
#define NSAMP 32
#define POS (NSAMP*SS)       // 16384 positions per batch; pos = s*32 + ns
#define PTOT (BB*POS)
#define R2 0.16f
#define NGRP 512             // POS/32 groups per batch; group g == centroid s

// Fragment layout (NEW, vector-friendly): seg = ((g*2+mt)*4+ks)
//   addr(seg, lane, reg) = seg*128 + lane*4 + reg   (uint32 = half2)
#define FRAG_BATCH (NGRP*2*4*4*32)   // 524288 uint32 per batch

// ---------------- scratch (device globals; no allocation allowed) ----------
__device__ uint32_t g_x0F[BB*FRAG_BATCH];   // raw W0*feat, fragment layout
__device__ uint32_t g_x1F[BB*FRAG_BATCH];   // raw W1*y1,   fragment layout
__device__ float g_gmax[BB*128*SS];         // [b][o][s]
__device__ float g_gmin[BB*128*SS];
__device__ float g_fs[6], g_gm[21];
__device__ float g_sum1[64], g_sq1[64];
__device__ float g_sum2[128], g_sq2[128];

// ---------------- helpers ---------------------------------------------------
__device__ __forceinline__ uint32_t smem_u32(const void* p) {
    return (uint32_t)__cvta_generic_to_shared(p);
}
__device__ __forceinline__ void mma_f16(float d[4], const uint32_t a[4],
                                        uint32_t b0, uint32_t b1) {
    asm volatile(
        "mma.sync.aligned.m16n8k16.row.col.f32.f16.f16.f32 "
        "{%0,%1,%2,%3}, {%4,%5,%6,%7}, {%8,%9}, {%0,%1,%2,%3};"
        : "+f"(d[0]), "+f"(d[1]), "+f"(d[2]), "+f"(d[3])
        : "r"(a[0]), "r"(a[1]), "r"(a[2]), "r"(a[3]), "r"(b0), "r"(b1));
}
#define LDSM_X2(r0,r1,addr) \
    asm volatile("ldmatrix.sync.aligned.m8n8.x2.shared.b16 {%0,%1}, [%2];" \
        : "=r"(r0), "=r"(r1) : "r"(addr))

// ---------------- FPS: 512 threads x 8 pts/thread --------------------------
extern "C" __global__ __launch_bounds__(512)
void fps_kernel(const float* __restrict__ xyz, float* __restrict__ out_xyz) {
    extern __shared__ float fsh[];
    float* sx = fsh;
    float* sy = fsh + NN;
    float* sz = fsh + 2 * NN;
    unsigned long long* sred = (unsigned long long*)(fsh + 3 * NN); // [2][32]=512B
    int* sfarh = (int*)(fsh + 3 * NN + 128);                        // [512]

    int t = threadIdx.x, b = blockIdx.x, lane = t & 31, warp = t >> 5; // 16 warps
    const float* xb = xyz + (size_t)b * 3 * NN;

    if (b == 0) {
        if (t < 21) g_gm[t] = 0.f;
        else if (t < 27) g_fs[t - 21] = 0.f;
        if (t < 64) { g_sum1[t] = 0.f; g_sq1[t] = 0.f; }
        if (t < 128){ g_sum2[t] = 0.f; g_sq2[t] = 0.f; }
    }
    if (t < 64) {
        int ph = t >> 5, sl = t & 31;
        if (sl >= 16) sred[ph * 32 + sl] = 0x00000000FFFFFFFFull;
    }

    float px[8], py[8], pz[8], dist[8];
#pragma unroll
    for (int k = 0; k < 8; k++) {
        int i = t + k * 512;
        float x = xb[i], y = xb[NN + i], z = xb[2 * NN + i];
        px[k] = x; py[k] = y; pz[k] = z;
        sx[i] = x; sy[i] = y; sz[i] = z;
        dist[k] = 1e10f;
    }
    __syncthreads();

    int far = 0;
    for (int s = 0; s < SS; s++) {
        if (t == 0) sfarh[s] = far;
        float cx = sx[far], cy = sy[far], cz = sz[far];
        float bv; int bi;
        {
            float dx = px[0]-cx, dy = py[0]-cy, dz = pz[0]-cz;
            float d = dx*dx + dy*dy + dz*dz;
            float nd = fminf(dist[0], d); dist[0] = nd;
            bv = nd; bi = t;
        }
#pragma unroll
        for (int k = 1; k < 8; k++) {
            float dx = px[k]-cx, dy = py[k]-cy, dz = pz[k]-cz;
            float d = dx*dx + dy*dy + dz*dz;
            float nd = fminf(dist[k], d); dist[k] = nd;
            if (nd > bv) { bv = nd; bi = t + k * 512; }
        }
        unsigned uv = __float_as_uint(bv);
        unsigned wm = __reduce_max_sync(0xffffffffu, uv);
        unsigned cand = (uv == wm) ? (unsigned)bi : 0xffffffffu;
        unsigned wi = __reduce_min_sync(0xffffffffu, cand);
        if (lane == 0)
            sred[(s & 1) * 32 + warp] = ((unsigned long long)wm << 32) | wi;
        __syncthreads();
        unsigned long long e = sred[(s & 1) * 32 + lane];
        unsigned v = (unsigned)(e >> 32), ix = (unsigned)e;
        unsigned m2 = __reduce_max_sync(0xffffffffu, v);
        unsigned c2 = (v == m2) ? ix : 0xffffffffu;
        far = (int)__reduce_min_sync(0xffffffffu, c2);
    }
    __syncthreads();
    if (t < SS) {
        int i = sfarh[t];
        out_xyz[(b * 3 + 0) * SS + t] = sx[i];
        out_xyz[(b * 3 + 1) * SS + t] = sy[i];
        out_xyz[(b * 3 + 2) * SS + t] = sz[i];
    }
}

// ---------------- ball query + fused layer0 (vector fragment layout) -------
#define BALL_SMEM_F (7*NN + 384 + 32*32*6 + 32*27)
extern "C" __global__ __launch_bounds__(1024)
void ball_kernel(const float* __restrict__ xyz, const float* __restrict__ pts,
                 const float* __restrict__ new_xyz, const float* __restrict__ w0) {
    extern __shared__ float sh[];
    float* sx   = sh;
    float* sy   = sh + NN;
    float* sz   = sh + 2 * NN;
    float* spp  = sh + 3 * NN;
    float* sp0  = sh + 4 * NN;
    float* sp1  = sh + 5 * NN;
    float* sp2  = sh + 6 * NN;
    float* sw   = sh + 7 * NN;
    float* swf  = sw + 384;
    float* sred = swf + 32 * 32 * 6;

    int b = blockIdx.x, chunk = blockIdx.y;
    int t = threadIdx.x;
    const float* xb = xyz + (size_t)b * 3 * NN;
    const float* pb = pts + (size_t)b * 3 * NN;

    if (t < 384) sw[t] = w0[t];
    for (int i = t; i < NN; i += 1024) {
        float x = xb[i], y = xb[NN + i], z = xb[2 * NN + i];
        sx[i] = x; sy[i] = y; sz[i] = z;
        spp[i] = x * x + y * y + z * z;
        sp0[i] = pb[i]; sp1[i] = pb[NN + i]; sp2[i] = pb[2 * NN + i];
    }
    __syncthreads();

    int lane = t & 31, warp = t >> 5;
    float* wslots = swf + warp * 192;

    float gm[21];
    float fs[6];
#pragma unroll
    for (int k = 0; k < 21; k++) gm[k] = 0.f;
#pragma unroll
    for (int k = 0; k < 6; k++) fs[k] = 0.f;

    uint32_t* x0b = g_x0F + (size_t)b * FRAG_BATCH;
    int mt = lane >> 4, gid8 = lane & 7, rh = (lane >> 3) & 1;

    for (int q = 0; q < 2; q++) {
        int s = chunk * 64 + q * 32 + warp;
        float cx = new_xyz[(b * 3 + 0) * SS + s];
        float cy = new_xyz[(b * 3 + 1) * SS + s];
        float cz = new_xyz[(b * 3 + 2) * SS + s];
        float cc = cx * cx + cy * cy + cz * cz;

        int count = 0;
        int first_i = 0;
        for (int base = 0; base < NN; base += 32) {
            int i = base + lane;
            float dot = cx * sx[i] + cy * sy[i] + cz * sz[i];
            float sum2 = __fadd_rn(cc, spp[i]);
            float sqr = __fsub_rn(sum2, 2.0f * dot);
            bool pred = (sqr <= R2);
            unsigned mask = __ballot_sync(0xffffffffu, pred);
            if (count == 0 && mask) {
                int src = __ffs(mask) - 1;
                first_i = __shfl_sync(0xffffffffu, i, src);
            }
            int rank = __popc(mask & ((1u << lane) - 1u));
            int slot = count + rank;
            if (pred && slot < NSAMP) {
                float* d = wslots + slot * 6;
                d[0] = sx[i] - cx; d[1] = sy[i] - cy; d[2] = sz[i] - cz;
                d[3] = sp0[i];     d[4] = sp1[i];     d[5] = sp2[i];
            }
            count += __popc(mask);
            if (count >= NSAMP) break;
        }
        if (count < NSAMP && lane >= count) {
            int i = first_i;
            float* d = wslots + lane * 6;
            d[0] = sx[i] - cx; d[1] = sy[i] - cy; d[2] = sz[i] - cz;
            d[3] = sp0[i];     d[4] = sp1[i];     d[5] = sp2[i];
        }
        __syncwarp();

        float f[6];
#pragma unroll
        for (int c = 0; c < 6; c++) f[c] = wslots[lane * 6 + c];
        {
            int k = 0;
#pragma unroll
            for (int c = 0; c < 6; c++) {
                fs[c] += f[c];
#pragma unroll
                for (int d = c; d < 6; d++) gm[k++] += f[c] * f[d];
            }
        }
#pragma unroll 2
        for (int jc = 0; jc < 8; jc++) {
            float v[8];
#pragma unroll
            for (int jj = 0; jj < 8; jj++) {
                int o = jc * 8 + jj;
                const float2* wr = (const float2*)&sw[o * 6];
                float2 w01 = wr[0], w23 = wr[1], w45 = wr[2];
                v[jj] = w01.x * f[0] + w01.y * f[1] + w23.x * f[2]
                      + w23.y * f[3] + w45.x * f[4] + w45.y * f[5];
            }
            int ks = jc >> 1, kh = jc & 1;
            int reg = kh * 2 + rh;
            size_t segb = (size_t)(((s * 2 + mt) * 4 + ks)) * 128;
#pragma unroll
            for (int i = 0; i < 4; i++) {
                __half2 h = __floats2half2_rn(v[2*i], v[2*i+1]);
                x0b[segb + (gid8 * 4 + i) * 4 + reg] = *(uint32_t*)&h;
            }
        }
        __syncwarp();
    }

#pragma unroll
    for (int k = 0; k < 21; k++)
#pragma unroll
        for (int off = 16; off; off >>= 1)
            gm[k] += __shfl_xor_sync(0xffffffffu, gm[k], off);
#pragma unroll
    for (int k = 0; k < 6; k++)
#pragma unroll
        for (int off = 16; off; off >>= 1)
            fs[k] += __shfl_xor_sync(0xffffffffu, fs[k], off);
    if (lane == 0) {
#pragma unroll
        for (int k = 0; k < 21; k++) sred[warp * 27 + k] = gm[k];
#pragma unroll
        for (int k = 0; k < 6; k++)  sred[warp * 27 + 21 + k] = fs[k];
    }
    __syncthreads();
    if (t < 27) {
        float v = 0.f;
#pragma unroll 8
        for (int w = 0; w < 32; w++) v += sred[w * 27 + t];
        if (t < 21) atomicAdd(&g_gm[t], v);
        else        atomicAdd(&g_fs[t - 21], v);
    }
}

// ---------------- fp16 mma kernels: BN folded into W, deferred stats -------
// y = relu(a*x+c) = a * relu(x + c/a)  (a>0);  W' = W * a (per input channel).
// BN mainloop cost: HADD2 + HMAX2 per half2 reg. Stats accumulate in regs
// across tiles; single reduction per CTA at the end.
template <int L>
__global__ __launch_bounds__(256, 1) void mma_layer_kernel(
    const float* __restrict__ w,       // w1 / w2 : [COUT][64]
    const float* __restrict__ w0,      // L=1 only (Gram matvec)
    const float* __restrict__ gg,      // g0 / g1
    const float* __restrict__ gbeta)   // beta0 / beta1
{
    constexpr int COUT  = (L == 1) ? 64 : 128;
    constexpr int TILES = (L == 1) ? 4 : 8;

    extern __shared__ __align__(16) char dsmc[];
    __half* sw = (__half*)dsmc;                          // [COUT][72]
    float* sred_s = (float*)(dsmc + COUT * 144);         // [8][64]
    float* sred_q = sred_s + 8 * 64;                     // [8][64]
    __shared__ float san[64], scn[64];   // a, c/a

    int t = threadIdx.x;
    int warp = t >> 5, lane = t & 31;
    int gid = lane >> 2, tig = lane & 3;

    int b = blockIdx.x >> 4, chunk = blockIdx.x & 15;
    int ob = (L == 1) ? 0 : (warp & 1) * 64;

    // ---- fused finalize of previous layer's BN: a and c/a ----
    const float invP = 1.0f / (float)PTOT;
    if (t < 64) {
        float m, var;
        if (L == 1) {
            float wv[6];
#pragma unroll
            for (int c = 0; c < 6; c++) wv[c] = w0[t * 6 + c];
            m = 0.f;
#pragma unroll
            for (int c = 0; c < 6; c++) m += wv[c] * g_fs[c];
            m *= invP;
            float e2 = 0.f;
            int k = 0;
#pragma unroll
            for (int c = 0; c < 6; c++)
#pragma unroll
                for (int d = c; d < 6; d++) {
                    float gcd = g_gm[k++];
                    e2 += (d == c) ? wv[c] * wv[c] * gcd
                                   : 2.f * wv[c] * wv[d] * gcd;
                }
            e2 *= invP;
            var = e2 - m * m;
        } else {
            m = g_sum1[t] * invP;
            var = g_sq1[t] * invP - m * m;
        }
        float av = gg[t] * rsqrtf(var + 1e-5f);     // a > 0 (g = 1)
        san[t] = av;
        scn[t] = gbeta[t] / av - m;                 // c/a
    }
    __syncthreads();

    // ---- stage W' = W * a -> half smem [n][72] ----
    for (int e = t; e < COUT * 8; e += 256) {
        int n = e >> 3, q = e & 7;
        const float4* wr = (const float4*)(w + n * 64 + q * 8);
        float4 wa = wr[0], wb = wr[1];
        int k0 = q * 8;
        uint4 u;
        uint32_t* up = (uint32_t*)&u;
        __half2 h0 = __floats2half2_rn(wa.x*san[k0+0], wa.y*san[k0+1]); up[0] = *(uint32_t*)&h0;
        __half2 h1 = __floats2half2_rn(wa.z*san[k0+2], wa.w*san[k0+3]); up[1] = *(uint32_t*)&h1;
        __half2 h2 = __floats2half2_rn(wb.x*san[k0+4], wb.y*san[k0+5]); up[2] = *(uint32_t*)&h2;
        __half2 h3 = __floats2half2_rn(wb.z*san[k0+6], wb.w*san[k0+7]); up[3] = *(uint32_t*)&h3;
        *(uint4*)&sw[n * 72 + q * 8] = u;
    }

    // ---- per-thread c/a half2 for this thread's 8 (ks,kh) channel pairs ----
    uint32_t ch2[8];
#pragma unroll
    for (int ks = 0; ks < 4; ks++)
#pragma unroll
        for (int kh = 0; kh < 2; kh++) {
            int c0 = ks * 16 + kh * 8 + tig * 2;
            __half2 h = __floats2half2_rn(scn[c0], scn[c0 + 1]);
            ch2[ks * 2 + kh] = *(uint32_t*)&h;
        }
    __syncthreads();

    const uint32_t* xin = ((L == 1) ? g_x0F : g_x1F) + (size_t)b * FRAG_BATCH;
    uint32_t* xout = g_x1F + (size_t)b * FRAG_BATCH;
    uint32_t sw_b = smem_u32(sw);
    int b_row  = ob + (lane & 7);
    int b_koff = ((lane >> 3) & 1) * 8;

    // ---- hoist B fragments (tile-invariant) ----
    uint32_t bfr[4][8][2];
#pragma unroll
    for (int ks = 0; ks < 4; ks++) {
        int k0 = ks * 16;
#pragma unroll
        for (int nt = 0; nt < 8; nt++) {
            uint32_t baddr = sw_b + (uint32_t)(((b_row + nt * 8) * 72 + k0 + b_koff) * 2);
            LDSM_X2(bfr[ks][nt][0], bfr[ks][nt][1], baddr);
        }
    }

    const __half2 hzero = __floats2half2_rn(0.f, 0.f);
    float sE[8], sO[8], qE[8], qO[8];
#pragma unroll
    for (int nt = 0; nt < 8; nt++) { sE[nt]=0.f; sO[nt]=0.f; qE[nt]=0.f; qO[nt]=0.f; }

    for (int tile = 0; tile < TILES; tile++) {
        int g = (L == 1) ? (chunk * 32 + tile * 8 + warp)
                         : (chunk * 32 + tile * 4 + (warp >> 1));

        // ---- A fragments: one LDG.128 per (mt, ks) ----
        uint32_t afr[2][4][4];
#pragma unroll
        for (int mt = 0; mt < 2; mt++)
#pragma unroll
            for (int ks = 0; ks < 4; ks++) {
                uint4 v = *(const uint4*)(xin
                    + (size_t)(((g * 2 + mt) * 4 + ks)) * 128 + lane * 4);
                afr[mt][ks][0] = v.x; afr[mt][ks][1] = v.y;
                afr[mt][ks][2] = v.z; afr[mt][ks][3] = v.w;
            }
        // ---- BN: (x + c/a), relu — pure half2 (2 instr per reg) ----
#pragma unroll
        for (int mt = 0; mt < 2; mt++)
#pragma unroll
            for (int ks = 0; ks < 4; ks++)
#pragma unroll
                for (int j = 0; j < 4; j++) {
                    __half2 h = *(__half2*)&afr[mt][ks][j];
                    h = __hmax2(__hadd2(h, *(__half2*)&ch2[ks * 2 + (j >> 1)]), hzero);
                    afr[mt][ks][j] = *(uint32_t*)&h;
                }

        // ---- MMA ----
        float acc[2][8][4];
#pragma unroll
        for (int mt = 0; mt < 2; mt++)
#pragma unroll
            for (int nt = 0; nt < 8; nt++)
#pragma unroll
                for (int k = 0; k < 4; k++) acc[mt][nt][k] = 0.f;
#pragma unroll
        for (int ks = 0; ks < 4; ks++)
#pragma unroll
            for (int nt = 0; nt < 8; nt++) {
                mma_f16(acc[0][nt], afr[0][ks], bfr[ks][nt][0], bfr[ks][nt][1]);
                mma_f16(acc[1][nt], afr[1][ks], bfr[ks][nt][0], bfr[ks][nt][1]);
            }

        // ---- stats accumulate (registers, deferred reduction) ----
#pragma unroll
        for (int nt = 0; nt < 8; nt++)
#pragma unroll
            for (int mt = 0; mt < 2; mt++) {
                float v0 = acc[mt][nt][0], v1 = acc[mt][nt][1];
                float v2 = acc[mt][nt][2], v3 = acc[mt][nt][3];
                sE[nt] += v0 + v2; sO[nt] += v1 + v3;
                qE[nt] += v0*v0 + v2*v2; qO[nt] += v1*v1 + v3*v3;
            }

        if (L == 1) {
            // D fragment -> next layer's A fragment: one STG.128 per (mt, ks)
#pragma unroll
            for (int mt = 0; mt < 2; mt++)
#pragma unroll
                for (int ks = 0; ks < 4; ks++) {
                    int ne = 2 * ks, no = 2 * ks + 1;
                    uint4 u;
                    __half2 h;
                    h = __floats2half2_rn(acc[mt][ne][0], acc[mt][ne][1]); u.x = *(uint32_t*)&h;
                    h = __floats2half2_rn(acc[mt][ne][2], acc[mt][ne][3]); u.y = *(uint32_t*)&h;
                    h = __floats2half2_rn(acc[mt][no][0], acc[mt][no][1]); u.z = *(uint32_t*)&h;
                    h = __floats2half2_rn(acc[mt][no][2], acc[mt][no][3]); u.w = *(uint32_t*)&h;
                    *(uint4*)(xout + (size_t)(((g * 2 + mt) * 4 + ks)) * 128 + lane * 4) = u;
                }
        } else {
            // fused 32-neighbor max/min pool
#pragma unroll
            for (int nt = 0; nt < 8; nt++) {
                float mxe = fmaxf(fmaxf(acc[0][nt][0], acc[0][nt][2]),
                                  fmaxf(acc[1][nt][0], acc[1][nt][2]));
                float mne = fminf(fminf(acc[0][nt][0], acc[0][nt][2]),
                                  fminf(acc[1][nt][0], acc[1][nt][2]));
                float mxo = fmaxf(fmaxf(acc[0][nt][1], acc[0][nt][3]),
                                  fmaxf(acc[1][nt][1], acc[1][nt][3]));
                float mno = fminf(fminf(acc[0][nt][1], acc[0][nt][3]),
                                  fminf(acc[1][nt][1], acc[1][nt][3]));
#pragma unroll
                for (int off = 4; off < 32; off <<= 1) {
                    mxe = fmaxf(mxe, __shfl_xor_sync(0xffffffffu, mxe, off));
                    mxo = fmaxf(mxo, __shfl_xor_sync(0xffffffffu, mxo, off));
                    mne = fminf(mne, __shfl_xor_sync(0xffffffffu, mne, off));
                    mno = fminf(mno, __shfl_xor_sync(0xffffffffu, mno, off));
                }
                if (gid == 0) {
                    int o = ob + nt * 8 + 2 * tig;
                    g_gmax[(size_t)(b * 128 + o) * SS + g]     = mxe;
                    g_gmax[(size_t)(b * 128 + o + 1) * SS + g] = mxo;
                    g_gmin[(size_t)(b * 128 + o) * SS + g]     = mne;
                    g_gmin[(size_t)(b * 128 + o + 1) * SS + g] = mno;
                }
            }
        }
    }

    // ---- one stats reduction per warp ----
#pragma unroll
    for (int nt = 0; nt < 8; nt++) {
#pragma unroll
        for (int off = 4; off < 32; off <<= 1) {
            sE[nt] += __shfl_xor_sync(0xffffffffu, sE[nt], off);
            sO[nt] += __shfl_xor_sync(0xffffffffu, sO[nt], off);
            qE[nt] += __shfl_xor_sync(0xffffffffu, qE[nt], off);
            qO[nt] += __shfl_xor_sync(0xffffffffu, qO[nt], off);
        }
        if (gid == 0) {
            int lc = nt * 8 + 2 * tig;
            sred_s[warp * 64 + lc]     = sE[nt];
            sred_s[warp * 64 + lc + 1] = sO[nt];
            sred_q[warp * 64 + lc]     = qE[nt];
            sred_q[warp * 64 + lc + 1] = qO[nt];
        }
    }
    __syncthreads();

    if (L == 1) {
        if (t < 64) {
            float s = 0.f;
#pragma unroll
            for (int w8 = 0; w8 < 8; w8++) s += sred_s[w8 * 64 + t];
            atomicAdd(&g_sum1[t], s);
        } else if (t < 128) {
            int c = t - 64;
            float q = 0.f;
#pragma unroll
            for (int w8 = 0; w8 < 8; w8++) q += sred_q[w8 * 64 + c];
            atomicAdd(&g_sq1[c], q);
        }
    } else {
        if (t < 128) {
            int par = t >> 6, lc = t & 63;
            float s = 0.f;
#pragma unroll
            for (int j = 0; j < 4; j++) s += sred_s[(2 * j + par) * 64 + lc];
            atomicAdd(&g_sum2[t], s);
        } else {
            int c = t - 128;
            int par = c >> 6, lc = c & 63;
            float q = 0.f;
#pragma unroll
            for (int j = 0; j < 4; j++) q += sred_q[(2 * j + par) * 64 + lc];
            atomicAdd(&g_sq2[c], q);
        }
    }
}

// ---------------- final: fused finalize2 + affine + relu on pooled ---------
__global__ __launch_bounds__(256) void final_kernel(float* __restrict__ out,
                                                    const float* __restrict__ g2,
                                                    const float* __restrict__ beta2) {
    int idx = blockIdx.x * 256 + threadIdx.x;   // (b,o,s)
    int o = (idx >> 9) & 127;
    const float invP = 1.0f / (float)PTOT;
    float m = g_sum2[o] * invP;
    float v = g_sq2[o] * invP - m * m;
    float av = g2[o] * rsqrtf(v + 1e-5f);
    float cv = beta2[o] - m * av;
    float mm = (av >= 0.f) ? g_gmax[idx] : g_gmin[idx];
    out[BB * 3 * SS + idx] = fmaxf(av * mm + cv, 0.f);
}

// ---------------- launch ----------------------------------------------------
extern "C" void kernel_launch(void* const* d_in, const int* in_sizes, int n_in,
                              void* d_out, int out_size) {
    const float* xyz   = (const float*)d_in[0];
    const float* pts   = (const float*)d_in[1];
    const float* w0    = (const float*)d_in[2];
    const float* g0    = (const float*)d_in[4];
    const float* beta0 = (const float*)d_in[5];
    const float* w1    = (const float*)d_in[6];
    const float* g1    = (const float*)d_in[8];
    const float* beta1 = (const float*)d_in[9];
    const float* w2    = (const float*)d_in[10];
    const float* g2    = (const float*)d_in[12];
    const float* beta2 = (const float*)d_in[13];
    float* out = (float*)d_out;

    const int FPS_SMEM = 3 * NN * 4 + 512 + SS * 4;
    const int SMEM_L1  = 64 * 144 + 2 * 8 * 64 * 4;    // ~13.3KB
    const int SMEM_L2  = 128 * 144 + 2 * 8 * 64 * 4;   // ~22.5KB

    cudaFuncSetAttribute(fps_kernel, cudaFuncAttributeMaxDynamicSharedMemorySize,
                         FPS_SMEM);
    cudaFuncSetAttribute(ball_kernel, cudaFuncAttributeMaxDynamicSharedMemorySize,
                         BALL_SMEM_F * 4);
    cudaFuncSetAttribute(mma_layer_kernel<1>, cudaFuncAttributeMaxDynamicSharedMemorySize,
                         SMEM_L1);
    cudaFuncSetAttribute(mma_layer_kernel<2>, cudaFuncAttributeMaxDynamicSharedMemorySize,
                         SMEM_L2);

    fps_kernel<<<BB, 512, FPS_SMEM>>>(xyz, out);
    ball_kernel<<<dim3(BB, 8), 1024, BALL_SMEM_F * 4>>>(xyz, pts, out, w0);
    mma_layer_kernel<1><<<256, 256, SMEM_L1>>>(w1, w0, g0, beta0);
    mma_layer_kernel<2><<<256, 256, SMEM_L2>>>(w2, w0, g1, beta1);
    final_kernel<<<(BB * 128 * SS) / 256, 256>>>(out, g2, beta2);
}